// round 1
// baseline (speedup 1.0000x reference)
#include <cuda_runtime.h>

// Problem constants (fixed by the reference generator)
#define NN   10000      // nodes
#define BB   2          // batch
#define FF   128        // F_IN
#define DD   128        // D_EMB
#define EPN  33         // edges per node (DEG+1), grouped contiguously by src
#define EE   (NN * EPN)

// Scratch (device globals — no cudaMalloc allowed)
__device__ float g_h[BB * NN * DD];   // projected features, 10.24 MB
__device__ float g_s[BB * NN];        // h @ a_src
__device__ float g_d[BB * NN];        // h @ a_dst

// ---------------------------------------------------------------------------
// Kernel A: h = X @ W for both batches; s = h@a_src, d = h@a_dst fused in.
// One block per row (B*N rows), 128 threads = one output column each.
// X row broadcast from smem; W columns read coalesced (W stays L1-resident).
// ---------------------------------------------------------------------------
__global__ __launch_bounds__(128)
void gemm_sd_kernel(const float* __restrict__ inputs,
                    const float* __restrict__ W,
                    const float* __restrict__ W_attn) {
    const int row = blockIdx.x;     // 0 .. B*N-1
    const int t   = threadIdx.x;    // 0 .. 127

    __shared__ float xs[FF];
    __shared__ float warp_s[4];
    __shared__ float warp_d[4];

    xs[t] = inputs[row * FF + t];
    __syncthreads();

    float acc = 0.0f;
#pragma unroll 16
    for (int k = 0; k < FF; ++k) {
        acc = fmaf(xs[k], W[k * DD + t], acc);
    }
    g_h[row * DD + t] = acc;

    // Fused projections: s = sum_t acc*a_src[t], d = sum_t acc*a_dst[t]
    float vs = acc * W_attn[t];        // a_src = W_attn[0:128]
    float vd = acc * W_attn[DD + t];   // a_dst = W_attn[128:256]
#pragma unroll
    for (int off = 16; off > 0; off >>= 1) {
        vs += __shfl_down_sync(0xFFFFFFFFu, vs, off);
        vd += __shfl_down_sync(0xFFFFFFFFu, vd, off);
    }
    const int lane = t & 31, wid = t >> 5;
    if (lane == 0) { warp_s[wid] = vs; warp_d[wid] = vd; }
    __syncthreads();
    if (t == 0) {
        g_s[row] = warp_s[0] + warp_s[1] + warp_s[2] + warp_s[3];
        g_d[row] = warp_d[0] + warp_d[1] + warp_d[2] + warp_d[3];
    }
}

// ---------------------------------------------------------------------------
// Kernel B: per-node attention + aggregation.
// Block n owns edges [n*33, (n+1)*33) (src == n for all of them).
//   score_b[e] = exp(clip(leaky_relu(s[b][src] + d[b][dst]), -2, 2))
//   denom      = sum_e score_0[e]            (batch 0 only, per reference!)
//   out[n][f]  = (1/denom) * sum_e (score_0[e]*h0[dst][f] + score_1[e]*h1[dst][f])
// Written to both batch slices of the output (reference broadcasts).
// ---------------------------------------------------------------------------
__global__ __launch_bounds__(128)
void gat_agg_kernel(const int* __restrict__ edges,
                    float* __restrict__ out) {
    const int n = blockIdx.x;       // node
    const int t = threadIdx.x;      // feature lane

    __shared__ int   dsts[EPN];
    __shared__ float w0[EPN];
    __shared__ float w1[EPN];
    __shared__ float inv_denom;

    if (t < EPN) {
        const int e   = n * EPN + t;
        const int src = edges[2 * e];
        const int dst = edges[2 * e + 1];
        dsts[t] = dst;

        float sc0 = g_s[src]      + g_d[dst];
        float sc1 = g_s[NN + src] + g_d[NN + dst];
        // leaky_relu(0.2)
        sc0 = (sc0 > 0.0f) ? sc0 : 0.2f * sc0;
        sc1 = (sc1 > 0.0f) ? sc1 : 0.2f * sc1;
        // clip to [-2, 2], then exp
        sc0 = expf(fminf(fmaxf(sc0, -2.0f), 2.0f));
        sc1 = expf(fminf(fmaxf(sc1, -2.0f), 2.0f));
        w0[t] = sc0;
        w1[t] = sc1;
    }
    __syncthreads();

    if (t == 0) {
        float dn = 0.0f;
#pragma unroll
        for (int e = 0; e < EPN; ++e) dn += w0[e];
        inv_denom = 1.0f / dn;
    }
    __syncthreads();

    const float inv = inv_denom;
    const float* __restrict__ h0 = g_h;
    const float* __restrict__ h1 = g_h + NN * DD;

    float acc = 0.0f;
#pragma unroll
    for (int e = 0; e < EPN; ++e) {
        const int d = dsts[e];
        acc = fmaf(w0[e], __ldg(&h0[d * DD + t]), acc);
        acc = fmaf(w1[e], __ldg(&h1[d * DD + t]), acc);
    }
    acc *= inv;

    out[n * DD + t]           = acc;   // batch 0
    out[NN * DD + n * DD + t] = acc;   // batch 1 (broadcast)
}

// ---------------------------------------------------------------------------
extern "C" void kernel_launch(void* const* d_in, const int* in_sizes, int n_in,
                              void* d_out, int out_size) {
    const float* inputs = (const float*)d_in[0];   // (2, 10000, 128)
    const float* W      = (const float*)d_in[1];   // (128, 128)
    const float* W_attn = (const float*)d_in[2];   // (256, 1)
    const int*   edges  = (const int*)d_in[3];     // (330000, 2)
    float*       out    = (float*)d_out;           // (2, 10000, 128)

    gemm_sd_kernel<<<BB * NN, 128>>>(inputs, W, W_attn);
    gat_agg_kernel<<<NN, 128>>>(edges, out);
}

// round 2
// speedup vs baseline: 1.3171x; 1.3171x over previous
#include <cuda_runtime.h>

// Problem constants (fixed by the reference generator)
#define NN   10000          // nodes
#define BB   2              // batch
#define FF   128            // F_IN
#define DD   128            // D_EMB
#define EPN  33             // edges per node (DEG+1), contiguous per src node
#define ROWS (BB * NN)      // 20000 rows of X / h

// GEMM tiling
#define BM   64             // rows per block
#define XP   130            // Xs pitch in floats (even, bank-staggered)
#define NBLK ((ROWS + BM - 1) / BM)   // 313
#define GEMM_SMEM (BM * XP * 4 + 64 * 128 * 8)   // Xs + Wp = 98816 B

// Scratch (device globals — no cudaMalloc allowed)
__device__ float g_h[BB * NN * DD];   // projected features (10.24 MB)
__device__ float g_s[ROWS];           // h @ a_src
__device__ float g_d[ROWS];           // h @ a_dst

__device__ __forceinline__ unsigned long long ffma2(unsigned long long a,
                                                    unsigned long long b,
                                                    unsigned long long c) {
    unsigned long long d;
    asm("fma.rn.f32x2 %0, %1, %2, %3;" : "=l"(d) : "l"(a), "l"(b), "l"(c));
    return d;
}
__device__ __forceinline__ unsigned long long pack2(float lo, float hi) {
    unsigned long long v;
    asm("mov.b64 %0, {%1, %2};" : "=l"(v) : "f"(lo), "f"(hi));
    return v;
}
__device__ __forceinline__ void unpack2(unsigned long long v, float& lo, float& hi) {
    asm("mov.b64 {%0, %1}, %2;" : "=f"(lo), "=f"(hi) : "l"(v));
}

extern __shared__ char smem_raw[];

// ---------------------------------------------------------------------------
// Kernel A: h = X @ W (20000x128 @ 128x128), s/d projections fused.
// 128 threads = 8(tr) x 16(tc); each thread computes an 8x8 output tile with
// f32x2 accumulators packed over k-pairs (lo = even-k partial, hi = odd-k).
// Wp smem layout: [k2][swz(col)] where swz swaps col bit-groups so that the
// 16-lane b-load (stride 8 cols) lands on 16 distinct banks.
// ---------------------------------------------------------------------------
__global__ __launch_bounds__(128)
void gemm_sd_kernel(const float* __restrict__ inputs,
                    const float* __restrict__ W,
                    const float* __restrict__ W_attn) {
    float* Xs = (float*)smem_raw;                                   // [BM][XP]
    unsigned long long* Wp =
        (unsigned long long*)(smem_raw + BM * XP * 4);              // [64][128]

    const int t  = threadIdx.x;
    const int rb = blockIdx.x * BM;

    // --- Load X tile (coalesced scalar LDG, conflict-free STS) ---
#pragma unroll 8
    for (int i = 0; i < 64; ++i) {          // 64*128 elems / 128 threads
        int f = t + i * 128;
        int r = f >> 7, k = f & 127;
        int gr = rb + r; if (gr >= ROWS) gr = ROWS - 1;  // clamp (tail block)
        Xs[r * XP + k] = inputs[gr * FF + k];
    }
    // --- Build Wp: Wp[k2*128 + swz(col)] = (W[2k2][col], W[2k2+1][col]) ---
#pragma unroll 8
    for (int i = 0; i < 64; ++i) {          // 8192 ull / 128 threads
        int f = t + i * 128;
        int k2 = f >> 7, col = f & 127;
        float lo = W[(2 * k2) * DD + col];
        float hi = W[(2 * k2 + 1) * DD + col];
        int swz = ((col & 7) << 4) | (col >> 3);
        Wp[k2 * 128 + swz] = pack2(lo, hi);
    }
    __syncthreads();

    const int tc = t & 15;    // column group (16)
    const int tr = t >> 4;    // row group (8)

    unsigned long long acc[8][8];
#pragma unroll
    for (int i = 0; i < 8; ++i)
#pragma unroll
        for (int j = 0; j < 8; ++j) acc[i][j] = 0ull;

#pragma unroll 1
    for (int k2 = 0; k2 < 64; ++k2) {
        unsigned long long a[8], b[8];
#pragma unroll
        for (int i = 0; i < 8; ++i)
            a[i] = *(const unsigned long long*)&Xs[(tr * 8 + i) * XP + 2 * k2];
#pragma unroll
        for (int j = 0; j < 8; ++j)
            b[j] = Wp[k2 * 128 + (j << 4) + tc];
#pragma unroll
        for (int i = 0; i < 8; ++i)
#pragma unroll
            for (int j = 0; j < 8; ++j)
                acc[i][j] = ffma2(a[i], b[j], acc[i][j]);
    }

    // --- Epilogue: unpack, store h, fused s/d row-projections ---
    float as[8], ad[8];
#pragma unroll
    for (int j = 0; j < 8; ++j) {
        as[j] = __ldg(&W_attn[tc * 8 + j]);        // a_src
        ad[j] = __ldg(&W_attn[DD + tc * 8 + j]);   // a_dst
    }

#pragma unroll
    for (int i = 0; i < 8; ++i) {
        float h[8];
#pragma unroll
        for (int j = 0; j < 8; ++j) {
            float lo, hi;
            unpack2(acc[i][j], lo, hi);
            h[j] = lo + hi;
        }
        const int gr = rb + tr * 8 + i;
        if (gr < ROWS) {
            float4 v0 = make_float4(h[0], h[1], h[2], h[3]);
            float4 v1 = make_float4(h[4], h[5], h[6], h[7]);
            *(float4*)&g_h[gr * DD + tc * 8]     = v0;
            *(float4*)&g_h[gr * DD + tc * 8 + 4] = v1;
        }
        float ps = 0.0f, pd = 0.0f;
#pragma unroll
        for (int j = 0; j < 8; ++j) {
            ps = fmaf(h[j], as[j], ps);
            pd = fmaf(h[j], ad[j], pd);
        }
        // reduce across the 16 tc-lanes (stays inside 16-lane group)
#pragma unroll
        for (int off = 1; off < 16; off <<= 1) {
            ps += __shfl_xor_sync(0xFFFFFFFFu, ps, off);
            pd += __shfl_xor_sync(0xFFFFFFFFu, pd, off);
        }
        if (tc == 0 && gr < ROWS) { g_s[gr] = ps; g_d[gr] = pd; }
    }
}

// ---------------------------------------------------------------------------
// Kernel B: per-node attention + aggregation, float4 gathers.
// Block n owns edges [n*33, (n+1)*33). Warp w handles edges e = w, w+4, ...
// Each lane loads one float4 of the 512B h row (LDG.128, fully coalesced).
// ---------------------------------------------------------------------------
__global__ __launch_bounds__(128)
void gat_agg_kernel(const int* __restrict__ edges,
                    float* __restrict__ out) {
    const int n    = blockIdx.x;
    const int t    = threadIdx.x;
    const int lane = t & 31;
    const int w    = t >> 5;

    __shared__ int    dsts[EPN];
    __shared__ float  w0s[EPN];
    __shared__ float  w1s[EPN];
    __shared__ float  inv_denom;
    __shared__ float4 part[4][32];

    if (t < EPN) {
        const int e   = n * EPN + t;
        const int src = edges[2 * e];
        const int dst = edges[2 * e + 1];
        dsts[t] = dst;

        float sc0 = g_s[src]      + g_d[dst];
        float sc1 = g_s[NN + src] + g_d[NN + dst];
        sc0 = (sc0 > 0.0f) ? sc0 : 0.2f * sc0;   // leaky_relu(0.2)
        sc1 = (sc1 > 0.0f) ? sc1 : 0.2f * sc1;
        sc0 = expf(fminf(fmaxf(sc0, -2.0f), 2.0f));
        sc1 = expf(fminf(fmaxf(sc1, -2.0f), 2.0f));
        w0s[t] = sc0;
        w1s[t] = sc1;
    }
    __syncthreads();

    if (t == 0) {
        float dn = 0.0f;
#pragma unroll
        for (int e = 0; e < EPN; ++e) dn += w0s[e];
        inv_denom = 1.0f / dn;
    }
    __syncthreads();

    const float4* __restrict__ h0 = (const float4*)g_h;
    const float4* __restrict__ h1 = (const float4*)(g_h + NN * DD);

    float4 acc = make_float4(0.f, 0.f, 0.f, 0.f);
    for (int e = w; e < EPN; e += 4) {
        const int d = dsts[e];
        const float c0 = w0s[e], c1 = w1s[e];
        float4 v0 = __ldg(&h0[d * 32 + lane]);
        float4 v1 = __ldg(&h1[d * 32 + lane]);
        acc.x = fmaf(c0, v0.x, fmaf(c1, v1.x, acc.x));
        acc.y = fmaf(c0, v0.y, fmaf(c1, v1.y, acc.y));
        acc.z = fmaf(c0, v0.z, fmaf(c1, v1.z, acc.z));
        acc.w = fmaf(c0, v0.w, fmaf(c1, v1.w, acc.w));
    }
    part[w][lane] = acc;
    __syncthreads();

    if (t < 32) {
        float4 a = part[0][t], b = part[1][t], c = part[2][t], d = part[3][t];
        const float inv = inv_denom;
        float4 r;
        r.x = (a.x + b.x + c.x + d.x) * inv;
        r.y = (a.y + b.y + c.y + d.y) * inv;
        r.z = (a.z + b.z + c.z + d.z) * inv;
        r.w = (a.w + b.w + c.w + d.w) * inv;
        ((float4*)(out + n * DD))[t]           = r;   // batch 0
        ((float4*)(out + NN * DD + n * DD))[t] = r;   // batch 1 (broadcast)
    }
}

// ---------------------------------------------------------------------------
extern "C" void kernel_launch(void* const* d_in, const int* in_sizes, int n_in,
                              void* d_out, int out_size) {
    const float* inputs = (const float*)d_in[0];   // (2, 10000, 128)
    const float* W      = (const float*)d_in[1];   // (128, 128)
    const float* W_attn = (const float*)d_in[2];   // (256, 1)
    const int*   edges  = (const int*)d_in[3];     // (330000, 2)
    float*       out    = (float*)d_out;           // (2, 10000, 128)

    cudaFuncSetAttribute(gemm_sd_kernel,
                         cudaFuncAttributeMaxDynamicSharedMemorySize, GEMM_SMEM);

    gemm_sd_kernel<<<NBLK, 128, GEMM_SMEM>>>(inputs, W, W_attn);
    gat_agg_kernel<<<NN, 128>>>(edges, out);
}

// round 3
// speedup vs baseline: 1.7317x; 1.3147x over previous
#include <cuda_runtime.h>
#include <cuda_fp16.h>

// Problem constants (fixed by the reference generator)
#define NN   10000          // nodes
#define BB   2              // batch
#define FF   128            // F_IN
#define DD   128            // D_EMB
#define EPN  33             // edges per node (DEG+1), contiguous per src node
#define ROWS (BB * NN)      // 20000 rows of X / h

// GEMM tiling
#define BM   64             // rows per block
#define TPB  256
#define XP   132            // Xs pitch (floats), 16B-aligned rows
#define NBLK ((ROWS + BM - 1) / BM)                 // 313
#define GEMM_SMEM (BM * XP * 4 + 64 * 128 * 8)      // Xs + Wp = 99328 B

// Scratch (device globals — no cudaMalloc allowed)
__device__ __half2 g_h0[NN * 64];   // h batch 0, fp16 (2.56 MB)
__device__ __half2 g_h1[NN * 64];   // h batch 1, fp16
__device__ float   g_s[ROWS];       // h @ a_src (fp32)
__device__ float   g_d[ROWS];       // h @ a_dst (fp32)

__device__ __forceinline__ void ffma2(unsigned long long& acc,
                                      unsigned long long a,
                                      unsigned long long b) {
    asm("fma.rn.f32x2 %0, %1, %2, %0;" : "+l"(acc) : "l"(a), "l"(b));
}
__device__ __forceinline__ unsigned long long pack2(float lo, float hi) {
    unsigned long long v;
    asm("mov.b64 %0, {%1, %2};" : "=l"(v) : "f"(lo), "f"(hi));
    return v;
}
__device__ __forceinline__ float sum2(unsigned long long v) {
    float lo, hi;
    asm("mov.b64 {%0, %1}, %2;" : "=f"(lo), "=f"(hi) : "l"(v));
    return lo + hi;
}

extern __shared__ char smem_raw[];

// ---------------------------------------------------------------------------
// Kernel A: h = X @ W (20000x128 @ 128x128) with fused s/d projections.
// 256 threads = 8 warps; warp tr owns rows [tr*8, tr*8+8), lane tc owns
// cols [tc*4, tc*4+4). f32x2 accumulators packed over k-pairs.
// Wp[k2][swz(col)] with swz = ((col&3)<<5)|(col>>2) makes the per-warp
// b-load (fixed j, tc=0..31) a stride-1 conflict-free ull access.
// a-loads are warp-uniform (broadcast).
// ---------------------------------------------------------------------------
__global__ __launch_bounds__(TPB, 2)
void gemm_sd_kernel(const float* __restrict__ inputs,
                    const float* __restrict__ W,
                    const float* __restrict__ W_attn) {
    float* Xs = (float*)smem_raw;                                  // [64][XP]
    unsigned long long* Wp =
        (unsigned long long*)(smem_raw + BM * XP * 4);             // [64][128]

    const int t  = threadIdx.x;
    const int rb = blockIdx.x * BM;

    // --- Load X tile: 2048 float4, coalesced ---
    const float4* in4 = (const float4*)inputs;
#pragma unroll
    for (int i = 0; i < 8; ++i) {
        int idx = t + i * TPB;
        int row = idx >> 5, c4 = idx & 31;
        int gr = rb + row; if (gr >= ROWS) gr = ROWS - 1;
        *(float4*)&Xs[row * XP + c4 * 4] = in4[gr * 32 + c4];
    }
    // --- Build Wp: (W[2k2][col], W[2k2+1][col]) at swizzled col ---
#pragma unroll
    for (int i = 0; i < 32; ++i) {
        int f = t + i * TPB;
        int k2 = f >> 7, col = f & 127;
        float lo = W[(2 * k2) * DD + col];
        float hi = W[(2 * k2 + 1) * DD + col];
        int swz = ((col & 3) << 5) | (col >> 2);
        Wp[k2 * 128 + swz] = pack2(lo, hi);
    }
    __syncthreads();

    const int tc = t & 31;    // lane: column group
    const int tr = t >> 5;    // warp: row group

    unsigned long long acc[8][4];
#pragma unroll
    for (int i = 0; i < 8; ++i)
#pragma unroll
        for (int j = 0; j < 4; ++j) acc[i][j] = 0ull;

#pragma unroll 2
    for (int k2 = 0; k2 < 64; ++k2) {
        unsigned long long a[8], b[4];
#pragma unroll
        for (int i = 0; i < 8; ++i)
            a[i] = *(const unsigned long long*)&Xs[(tr * 8 + i) * XP + 2 * k2];
#pragma unroll
        for (int j = 0; j < 4; ++j)
            b[j] = Wp[k2 * 128 + (j << 5) + tc];
#pragma unroll
        for (int i = 0; i < 8; ++i)
#pragma unroll
            for (int j = 0; j < 4; ++j)
                ffma2(acc[i][j], a[i], b[j]);
    }

    // --- Epilogue: h (fp16 store), fused s/d projections (fp32) ---
    float as[4], ad[4];
#pragma unroll
    for (int j = 0; j < 4; ++j) {
        as[j] = __ldg(&W_attn[tc * 4 + j]);
        ad[j] = __ldg(&W_attn[DD + tc * 4 + j]);
    }

#pragma unroll
    for (int i = 0; i < 8; ++i) {
        float h[4];
#pragma unroll
        for (int j = 0; j < 4; ++j) h[j] = sum2(acc[i][j]);

        const int gr = rb + tr * 8 + i;
        if (gr < ROWS) {
            __half2 p0 = __floats2half2_rn(h[0], h[1]);
            __half2 p1 = __floats2half2_rn(h[2], h[3]);
            uint2 pk;
            pk.x = *(unsigned*)&p0;
            pk.y = *(unsigned*)&p1;
            if (gr < NN) ((uint2*)g_h0)[gr * 32 + tc] = pk;
            else         ((uint2*)g_h1)[(gr - NN) * 32 + tc] = pk;
        }

        float ps = 0.0f, pd = 0.0f;
#pragma unroll
        for (int j = 0; j < 4; ++j) {
            ps = fmaf(h[j], as[j], ps);
            pd = fmaf(h[j], ad[j], pd);
        }
#pragma unroll
        for (int off = 16; off > 0; off >>= 1) {
            ps += __shfl_xor_sync(0xFFFFFFFFu, ps, off);
            pd += __shfl_xor_sync(0xFFFFFFFFu, pd, off);
        }
        if (tc == 0 && gr < ROWS) { g_s[gr] = ps; g_d[gr] = pd; }
    }
}

// ---------------------------------------------------------------------------
// Kernel B: per-node attention + aggregation, fp16 gathers (256 B/row/batch).
// Block n owns edges [n*33, (n+1)*33). Lane owns features [lane*4, lane*4+4).
// Per edge: one LDG.64 from each batch's h row (fully coalesced 256 B).
// ---------------------------------------------------------------------------
__global__ __launch_bounds__(128)
void gat_agg_kernel(const int* __restrict__ edges,
                    float* __restrict__ out) {
    const int n    = blockIdx.x;
    const int t    = threadIdx.x;
    const int lane = t & 31;
    const int w    = t >> 5;

    __shared__ int    dsts[EPN];
    __shared__ float  w0s[EPN];
    __shared__ float  w1s[EPN];
    __shared__ float  inv_denom;
    __shared__ float4 part[4][32];

    if (t < EPN) {
        const int e   = n * EPN + t;
        const int src = edges[2 * e];
        const int dst = edges[2 * e + 1];
        dsts[t] = dst;

        float sc0 = g_s[src]      + g_d[dst];
        float sc1 = g_s[NN + src] + g_d[NN + dst];
        sc0 = (sc0 > 0.0f) ? sc0 : 0.2f * sc0;   // leaky_relu(0.2)
        sc1 = (sc1 > 0.0f) ? sc1 : 0.2f * sc1;
        sc0 = expf(fminf(fmaxf(sc0, -2.0f), 2.0f));
        sc1 = expf(fminf(fmaxf(sc1, -2.0f), 2.0f));
        w0s[t] = sc0;
        w1s[t] = sc1;
    }
    __syncthreads();

    if (t == 0) {
        float dn = 0.0f;
#pragma unroll
        for (int e = 0; e < EPN; ++e) dn += w0s[e];
        inv_denom = 1.0f / dn;
    }
    __syncthreads();

    const uint2* __restrict__ h0 = (const uint2*)g_h0;
    const uint2* __restrict__ h1 = (const uint2*)g_h1;

    float4 acc = make_float4(0.f, 0.f, 0.f, 0.f);
    for (int e = w; e < EPN; e += 4) {
        const int d = dsts[e];
        const float c0 = w0s[e], c1 = w1s[e];
        uint2 v0 = __ldg(&h0[d * 32 + lane]);
        uint2 v1 = __ldg(&h1[d * 32 + lane]);
        float2 f0a = __half22float2(*(__half2*)&v0.x);
        float2 f0b = __half22float2(*(__half2*)&v0.y);
        float2 f1a = __half22float2(*(__half2*)&v1.x);
        float2 f1b = __half22float2(*(__half2*)&v1.y);
        acc.x = fmaf(c0, f0a.x, fmaf(c1, f1a.x, acc.x));
        acc.y = fmaf(c0, f0a.y, fmaf(c1, f1a.y, acc.y));
        acc.z = fmaf(c0, f0b.x, fmaf(c1, f1b.x, acc.z));
        acc.w = fmaf(c0, f0b.y, fmaf(c1, f1b.y, acc.w));
    }
    part[w][lane] = acc;
    __syncthreads();

    if (t < 32) {
        float4 a = part[0][t], b = part[1][t], c = part[2][t], d = part[3][t];
        const float inv = inv_denom;
        float4 r;
        r.x = (a.x + b.x + c.x + d.x) * inv;
        r.y = (a.y + b.y + c.y + d.y) * inv;
        r.z = (a.z + b.z + c.z + d.z) * inv;
        r.w = (a.w + b.w + c.w + d.w) * inv;
        ((float4*)(out + n * DD))[t]           = r;   // batch 0
        ((float4*)(out + NN * DD + n * DD))[t] = r;   // batch 1 (broadcast)
    }
}

// ---------------------------------------------------------------------------
extern "C" void kernel_launch(void* const* d_in, const int* in_sizes, int n_in,
                              void* d_out, int out_size) {
    const float* inputs = (const float*)d_in[0];   // (2, 10000, 128)
    const float* W      = (const float*)d_in[1];   // (128, 128)
    const float* W_attn = (const float*)d_in[2];   // (256, 1)
    const int*   edges  = (const int*)d_in[3];     // (330000, 2)
    float*       out    = (float*)d_out;           // (2, 10000, 128)

    cudaFuncSetAttribute(gemm_sd_kernel,
                         cudaFuncAttributeMaxDynamicSharedMemorySize, GEMM_SMEM);

    gemm_sd_kernel<<<NBLK, TPB, GEMM_SMEM>>>(inputs, W, W_attn);
    gat_agg_kernel<<<NN, 128>>>(edges, out);
}

// round 4
// speedup vs baseline: 2.6195x; 1.5127x over previous
#include <cuda_runtime.h>
#include <cuda_fp16.h>

// Problem constants (fixed by the reference generator)
#define NN   10000          // nodes
#define BB   2              // batch
#define FF   128            // F_IN
#define DD   128            // D_EMB
#define EPN  33             // edges per node (DEG+1), contiguous per src node
#define ROWS (BB * NN)      // 20000 rows of X / h

// GEMM tiling
#define GBM  128
#define GNBLK ((ROWS + GBM - 1) / GBM)   // 157 -> single wave on 148 SMs
#define XPITCH 136                        // halves per smem row (bank-staggered)

// Scratch (device globals — no cudaMalloc allowed)
// Interleaved h: g_hx[node*32 + grp] = {b0 cols(4g,4g+1), b0 cols(4g+2,4g+3),
//                                       b1 cols(4g,4g+1), b1 cols(4g+2,4g+3)} as half2s
__device__ uint4 g_hx[NN * 32];     // 5.12 MB, both batches interleaved
__device__ float g_s[ROWS];         // h @ a_src (fp32)
__device__ float g_d[ROWS];         // h @ a_dst (fp32)

__device__ __forceinline__ unsigned packh2(float lo, float hi) {
    __half2 h = __floats2half2_rn(lo, hi);
    return *(unsigned*)&h;
}

// ---------------------------------------------------------------------------
// Kernel A: h = X @ W via mma.sync.m16n8k16 (fp16 in, fp32 acc).
// 128 threads = 4 warps; warp w owns cols [w*32, w*32+32) (4 n-tiles of 8).
// Block owns 128 rows (8 m-tiles of 16). W fragments live in registers
// (loaded once); X tile staged fp32->fp16 in smem. s/d projections fused.
// ---------------------------------------------------------------------------
__global__ __launch_bounds__(128)
void gemm_sd_kernel(const float* __restrict__ inputs,
                    const float* __restrict__ W,
                    const float* __restrict__ W_attn) {
    __shared__ __half Xs[GBM][XPITCH];
    __shared__ float sd_s[4][GBM];
    __shared__ float sd_d[4][GBM];

    const int t    = threadIdx.x;
    const int lane = t & 31;
    const int w    = t >> 5;
    const int rb   = blockIdx.x * GBM;
    const int g    = lane >> 2;      // group id (0..7)
    const int tg   = lane & 3;       // thread in group
    const int wcol = w * 32;

    // --- Stage X tile: fp32 global -> fp16 smem (row r by warp r%4) ---
#pragma unroll 4
    for (int i = 0; i < 32; ++i) {
        int r  = i * 4 + w;
        int gr = rb + r; if (gr >= ROWS) gr = ROWS - 1;
        float4 v = ((const float4*)inputs)[gr * 32 + lane];
        uint2 pk = make_uint2(packh2(v.x, v.y), packh2(v.z, v.w));
        *(uint2*)&Xs[r][lane * 4] = pk;
    }

    // --- Load W fragments into registers (col-major B frag for m16n8k16) ---
    // b[nt][kt][0] = {W[k0][c], W[k0+1][c]},  b[..][1] = {W[k0+8][c], W[k0+9][c]}
    unsigned bf[4][8][2];
#pragma unroll
    for (int nt = 0; nt < 4; ++nt) {
        const int c = wcol + nt * 8 + g;
#pragma unroll
        for (int kt = 0; kt < 8; ++kt) {
            const int k0 = kt * 16 + tg * 2;
            bf[nt][kt][0] = packh2(W[k0 * DD + c],       W[(k0 + 1) * DD + c]);
            bf[nt][kt][1] = packh2(W[(k0 + 8) * DD + c], W[(k0 + 9) * DD + c]);
        }
    }
    // a_src / a_dst values for this thread's output columns
    float as[4][2], ad[4][2];
#pragma unroll
    for (int nt = 0; nt < 4; ++nt) {
        const int c = wcol + nt * 8 + tg * 2;
        as[nt][0] = W_attn[c];       as[nt][1] = W_attn[c + 1];
        ad[nt][0] = W_attn[DD + c];  ad[nt][1] = W_attn[DD + c + 1];
    }
    __syncthreads();

    // --- Main loop over 8 m-tiles ---
#pragma unroll 1
    for (int mt = 0; mt < 8; ++mt) {
        float acc[4][4];
#pragma unroll
        for (int nt = 0; nt < 4; ++nt)
#pragma unroll
            for (int i = 0; i < 4; ++i) acc[nt][i] = 0.0f;

#pragma unroll
        for (int kt = 0; kt < 8; ++kt) {
            const int r0 = mt * 16 + g;
            const int c0 = kt * 16 + tg * 2;
            unsigned a0 = *(const unsigned*)&Xs[r0][c0];
            unsigned a1 = *(const unsigned*)&Xs[r0 + 8][c0];
            unsigned a2 = *(const unsigned*)&Xs[r0][c0 + 8];
            unsigned a3 = *(const unsigned*)&Xs[r0 + 8][c0 + 8];
#pragma unroll
            for (int nt = 0; nt < 4; ++nt) {
                asm volatile(
                    "mma.sync.aligned.m16n8k16.row.col.f32.f16.f16.f32 "
                    "{%0,%1,%2,%3}, {%4,%5,%6,%7}, {%8,%9}, {%0,%1,%2,%3};"
                    : "+f"(acc[nt][0]), "+f"(acc[nt][1]),
                      "+f"(acc[nt][2]), "+f"(acc[nt][3])
                    : "r"(a0), "r"(a1), "r"(a2), "r"(a3),
                      "r"(bf[nt][kt][0]), "r"(bf[nt][kt][1]));
            }
        }

        // --- Epilogue: interleaved fp16 h store + s/d partials ---
        const int row0 = rb + mt * 16 + g;       // and row0 + 8
#pragma unroll
        for (int nt = 0; nt < 4; ++nt) {
            const int colbase = wcol + nt * 8 + tg * 2;
            const int grp  = colbase >> 2;
            const int slot = (colbase >> 1) & 1;
            unsigned p0 = packh2(acc[nt][0], acc[nt][1]);   // row0
            unsigned p1 = packh2(acc[nt][2], acc[nt][3]);   // row0+8
            if (row0 < ROWS) {
                int b = row0 >= NN, node = row0 - b * NN;
                ((unsigned*)g_hx)[(node * 32 + grp) * 4 + b * 2 + slot] = p0;
            }
            if (row0 + 8 < ROWS) {
                int r1 = row0 + 8;
                int b = r1 >= NN, node = r1 - b * NN;
                ((unsigned*)g_hx)[(node * 32 + grp) * 4 + b * 2 + slot] = p1;
            }
        }

        float ps0 = 0.f, pd0 = 0.f, ps1 = 0.f, pd1 = 0.f;
#pragma unroll
        for (int nt = 0; nt < 4; ++nt) {
            ps0 = fmaf(acc[nt][0], as[nt][0], fmaf(acc[nt][1], as[nt][1], ps0));
            pd0 = fmaf(acc[nt][0], ad[nt][0], fmaf(acc[nt][1], ad[nt][1], pd0));
            ps1 = fmaf(acc[nt][2], as[nt][0], fmaf(acc[nt][3], as[nt][1], ps1));
            pd1 = fmaf(acc[nt][2], ad[nt][0], fmaf(acc[nt][3], ad[nt][1], pd1));
        }
        // reduce across the quad (lanes sharing g)
#pragma unroll
        for (int off = 1; off <= 2; off <<= 1) {
            ps0 += __shfl_xor_sync(0xFFFFFFFFu, ps0, off);
            pd0 += __shfl_xor_sync(0xFFFFFFFFu, pd0, off);
            ps1 += __shfl_xor_sync(0xFFFFFFFFu, ps1, off);
            pd1 += __shfl_xor_sync(0xFFFFFFFFu, pd1, off);
        }
        if (tg == 0) {
            sd_s[w][mt * 16 + g]     = ps0;
            sd_d[w][mt * 16 + g]     = pd0;
            sd_s[w][mt * 16 + g + 8] = ps1;
            sd_d[w][mt * 16 + g + 8] = pd1;
        }
    }
    __syncthreads();

    // final s/d reduce across warps (t = local row)
    {
        float s = sd_s[0][t] + sd_s[1][t] + sd_s[2][t] + sd_s[3][t];
        float d = sd_d[0][t] + sd_d[1][t] + sd_d[2][t] + sd_d[3][t];
        int gr = rb + t;
        if (gr < ROWS) { g_s[gr] = s; g_d[gr] = d; }
    }
}

// ---------------------------------------------------------------------------
// Kernel B: warp-per-node attention + aggregation.
// Lane j computes the score for edge j (edge 32 = last edge handled by all,
// via a broadcast load). Gather: lane owns feature group `lane`; one LDG.128
// per edge pulls both batches' 4 features (interleaved layout). No barriers.
// ---------------------------------------------------------------------------
__global__ __launch_bounds__(256)
void gat_agg_kernel(const int* __restrict__ edges,
                    float* __restrict__ out) {
    const int t    = threadIdx.x;
    const int lane = t & 31;
    const int wi   = t >> 5;
    const int n    = blockIdx.x * 8 + wi;

    // --- Scores: lane j handles edge n*33 + j ---
    const int2 e2 = __ldg(&((const int2*)edges)[n * EPN + lane]);
    const int dstv = e2.y;
    const float s0 = __ldg(&g_s[n]);
    const float s1 = __ldg(&g_s[NN + n]);

    float sc0 = s0 + __ldg(&g_d[dstv]);
    float sc1 = s1 + __ldg(&g_d[NN + dstv]);
    sc0 = (sc0 > 0.0f) ? sc0 : 0.2f * sc0;   // leaky_relu(0.2)
    sc1 = (sc1 > 0.0f) ? sc1 : 0.2f * sc1;
    float w0v = __expf(fminf(fmaxf(sc0, -2.0f), 2.0f));
    float w1v = __expf(fminf(fmaxf(sc1, -2.0f), 2.0f));
    // exact exp (expf) for accuracy:
    w0v = expf(fminf(fmaxf(sc0, -2.0f), 2.0f));
    w1v = expf(fminf(fmaxf(sc1, -2.0f), 2.0f));

    // edge 32 (broadcast load, same address for all lanes)
    const int d32 = __ldg(&edges[(n * EPN + 32) * 2 + 1]);
    float sx0 = s0 + __ldg(&g_d[d32]);
    float sx1 = s1 + __ldg(&g_d[NN + d32]);
    sx0 = (sx0 > 0.0f) ? sx0 : 0.2f * sx0;
    sx1 = (sx1 > 0.0f) ? sx1 : 0.2f * sx1;
    const float w032 = expf(fminf(fmaxf(sx0, -2.0f), 2.0f));
    const float w132 = expf(fminf(fmaxf(sx1, -2.0f), 2.0f));

    // denom = sum of batch-0 scores over all 33 edges
    float dn = w0v;
#pragma unroll
    for (int off = 16; off > 0; off >>= 1)
        dn += __shfl_xor_sync(0xFFFFFFFFu, dn, off);
    dn += w032;
    const float inv = 1.0f / dn;

    // --- Gather: 33 edges, one uint4 per edge per lane ---
    const uint4* __restrict__ hb = g_hx;
    float4 acc = make_float4(0.f, 0.f, 0.f, 0.f);

#pragma unroll
    for (int j = 0; j < 32; ++j) {
        const int   dj = __shfl_sync(0xFFFFFFFFu, dstv, j);
        const float c0 = __shfl_sync(0xFFFFFFFFu, w0v, j);
        const float c1 = __shfl_sync(0xFFFFFFFFu, w1v, j);
        uint4 v = __ldg(&hb[dj * 32 + lane]);
        float2 f0a = __half22float2(*(__half2*)&v.x);
        float2 f0b = __half22float2(*(__half2*)&v.y);
        float2 f1a = __half22float2(*(__half2*)&v.z);
        float2 f1b = __half22float2(*(__half2*)&v.w);
        acc.x = fmaf(c0, f0a.x, fmaf(c1, f1a.x, acc.x));
        acc.y = fmaf(c0, f0a.y, fmaf(c1, f1a.y, acc.y));
        acc.z = fmaf(c0, f0b.x, fmaf(c1, f1b.x, acc.z));
        acc.w = fmaf(c0, f0b.y, fmaf(c1, f1b.y, acc.w));
    }
    {   // edge 32
        uint4 v = __ldg(&hb[d32 * 32 + lane]);
        float2 f0a = __half22float2(*(__half2*)&v.x);
        float2 f0b = __half22float2(*(__half2*)&v.y);
        float2 f1a = __half22float2(*(__half2*)&v.z);
        float2 f1b = __half22float2(*(__half2*)&v.w);
        acc.x = fmaf(w032, f0a.x, fmaf(w132, f1a.x, acc.x));
        acc.y = fmaf(w032, f0a.y, fmaf(w132, f1a.y, acc.y));
        acc.z = fmaf(w032, f0b.x, fmaf(w132, f1b.x, acc.z));
        acc.w = fmaf(w032, f0b.y, fmaf(w132, f1b.y, acc.w));
    }

    float4 r;
    r.x = acc.x * inv; r.y = acc.y * inv; r.z = acc.z * inv; r.w = acc.w * inv;
    ((float4*)(out + n * DD))[lane]           = r;   // batch 0
    ((float4*)(out + NN * DD + n * DD))[lane] = r;   // batch 1 (broadcast)
}

// ---------------------------------------------------------------------------
extern "C" void kernel_launch(void* const* d_in, const int* in_sizes, int n_in,
                              void* d_out, int out_size) {
    const float* inputs = (const float*)d_in[0];   // (2, 10000, 128)
    const float* W      = (const float*)d_in[1];   // (128, 128)
    const float* W_attn = (const float*)d_in[2];   // (256, 1)
    const int*   edges  = (const int*)d_in[3];     // (330000, 2)
    float*       out    = (float*)d_out;           // (2, 10000, 128)

    gemm_sd_kernel<<<GNBLK, 128>>>(inputs, W, W_attn);
    gat_agg_kernel<<<NN / 8, 256>>>(edges, out);
}

// round 5
// speedup vs baseline: 3.2886x; 1.2554x over previous
#include <cuda_runtime.h>
#include <cuda_fp16.h>

// Problem constants (fixed by the reference generator)
#define NN   10000          // nodes
#define BB   2              // batch
#define FF   128            // F_IN
#define DD   128            // D_EMB
#define EPN  33             // edges per node (DEG+1), contiguous per src node
#define ROWS (BB * NN)      // 20000 rows of X / h

// GEMM tiling: 160 rows/block -> exactly 125 blocks (single wave on 148 SMs)
#define GBM    160
#define GTPB   256
#define GNBLK  (ROWS / GBM)          // 125
#define XPITCH 136                   // halves per smem row (bank-staggered)
#define XS_BYTES  (GBM * XPITCH * 2)            // 43520
#define GEMM_SMEM (XS_BYTES + 2 * 8 * GBM * 4)  // + sd partials = 53760

// Scratch (device globals — no cudaMalloc allowed)
// Interleaved h: g_hx[node*32 + grp] = {b0 h2(4g,4g+1), b0 h2(4g+2,4g+3),
//                                       b1 h2(4g,4g+1), b1 h2(4g+2,4g+3)}
__device__ uint4 g_hx[NN * 32];     // 5.12 MB, both batches interleaved
__device__ float g_s[ROWS];         // h @ a_src (fp32)
__device__ float g_d[ROWS];         // h @ a_dst (fp32)

__device__ __forceinline__ unsigned packh2(float lo, float hi) {
    __half2 h = __floats2half2_rn(lo, hi);
    return *(unsigned*)&h;
}
__device__ __forceinline__ void ffma2(unsigned long long& acc,
                                      unsigned long long a,
                                      unsigned long long b) {
    asm("fma.rn.f32x2 %0, %1, %2, %0;" : "+l"(acc) : "l"(a), "l"(b));
}
__device__ __forceinline__ unsigned long long packf2(float lo, float hi) {
    unsigned long long v;
    asm("mov.b64 %0, {%1, %2};" : "=l"(v) : "f"(lo), "f"(hi));
    return v;
}
__device__ __forceinline__ float2 unpackf2(unsigned long long v) {
    float2 r;
    asm("mov.b64 {%0, %1}, %2;" : "=f"(r.x), "=f"(r.y) : "l"(v));
    return r;
}

extern __shared__ char smem_raw[];

// ---------------------------------------------------------------------------
// Kernel A: h = X @ W via mma.sync.m16n8k16 (fp16 in, fp32 acc).
// 256 threads = 8 warps; warp w owns cols [w*16, w*16+16) (2 n-tiles).
// Block owns 160 rows (10 m-tiles). W fragments register-resident.
// s/d projections fused in the epilogue.
// ---------------------------------------------------------------------------
__global__ __launch_bounds__(GTPB)
void gemm_sd_kernel(const float* __restrict__ inputs,
                    const float* __restrict__ W,
                    const float* __restrict__ W_attn) {
    __half (*Xs)[XPITCH] = (__half(*)[XPITCH])smem_raw;
    float* sd_s = (float*)(smem_raw + XS_BYTES);   // [8][GBM]
    float* sd_d = sd_s + 8 * GBM;

    const int t    = threadIdx.x;
    const int lane = t & 31;
    const int w    = t >> 5;
    const int rb   = blockIdx.x * GBM;
    const int g    = lane >> 2;      // 0..7
    const int tg   = lane & 3;       // 0..3
    const int wcol = w * 16;

    // --- Stage X tile: fp32 global -> fp16 smem (coalesced, MLP=20) ---
#pragma unroll
    for (int i = 0; i < 20; ++i) {
        int idx = t + i * GTPB;
        int row = idx >> 5, c4 = idx & 31;
        float4 v = ((const float4*)inputs)[(rb + row) * 32 + c4];
        *(uint2*)&Xs[row][c4 * 4] =
            make_uint2(packh2(v.x, v.y), packh2(v.z, v.w));
    }

    // --- W fragments (col-major B frag for m16n8k16), register-resident ---
    unsigned bf[2][8][2];
#pragma unroll
    for (int nt = 0; nt < 2; ++nt) {
        const int c = wcol + nt * 8 + g;
#pragma unroll
        for (int kt = 0; kt < 8; ++kt) {
            const int k0 = kt * 16 + tg * 2;
            bf[nt][kt][0] = packh2(W[k0 * DD + c],       W[(k0 + 1) * DD + c]);
            bf[nt][kt][1] = packh2(W[(k0 + 8) * DD + c], W[(k0 + 9) * DD + c]);
        }
    }
    float as[2][2], ad[2][2];
#pragma unroll
    for (int nt = 0; nt < 2; ++nt) {
        const int c = wcol + nt * 8 + tg * 2;
        as[nt][0] = W_attn[c];       as[nt][1] = W_attn[c + 1];
        ad[nt][0] = W_attn[DD + c];  ad[nt][1] = W_attn[DD + c + 1];
    }
    __syncthreads();

    // --- Main loop over 10 m-tiles ---
#pragma unroll 1
    for (int mt = 0; mt < 10; ++mt) {
        float acc[2][4];
#pragma unroll
        for (int nt = 0; nt < 2; ++nt)
#pragma unroll
            for (int i = 0; i < 4; ++i) acc[nt][i] = 0.0f;

#pragma unroll
        for (int kt = 0; kt < 8; ++kt) {
            const int r0 = mt * 16 + g;
            const int c0 = kt * 16 + tg * 2;
            unsigned a0 = *(const unsigned*)&Xs[r0][c0];
            unsigned a1 = *(const unsigned*)&Xs[r0 + 8][c0];
            unsigned a2 = *(const unsigned*)&Xs[r0][c0 + 8];
            unsigned a3 = *(const unsigned*)&Xs[r0 + 8][c0 + 8];
#pragma unroll
            for (int nt = 0; nt < 2; ++nt) {
                asm volatile(
                    "mma.sync.aligned.m16n8k16.row.col.f32.f16.f16.f32 "
                    "{%0,%1,%2,%3}, {%4,%5,%6,%7}, {%8,%9}, {%0,%1,%2,%3};"
                    : "+f"(acc[nt][0]), "+f"(acc[nt][1]),
                      "+f"(acc[nt][2]), "+f"(acc[nt][3])
                    : "r"(a0), "r"(a1), "r"(a2), "r"(a3),
                      "r"(bf[nt][kt][0]), "r"(bf[nt][kt][1]));
            }
        }

        // --- Epilogue: interleaved fp16 h store + s/d partials ---
        const int row0 = rb + mt * 16 + g;      // and row0 + 8; all < ROWS
#pragma unroll
        for (int nt = 0; nt < 2; ++nt) {
            const int colbase = wcol + nt * 8 + tg * 2;
            const int grp  = colbase >> 2;
            const int slot = (colbase >> 1) & 1;
            unsigned p0 = packh2(acc[nt][0], acc[nt][1]);   // row0
            unsigned p1 = packh2(acc[nt][2], acc[nt][3]);   // row0+8
            {
                int b = row0 >= NN, node = row0 - b * NN;
                ((unsigned*)g_hx)[(node * 32 + grp) * 4 + b * 2 + slot] = p0;
            }
            {
                int r1 = row0 + 8;
                int b = r1 >= NN, node = r1 - b * NN;
                ((unsigned*)g_hx)[(node * 32 + grp) * 4 + b * 2 + slot] = p1;
            }
        }

        float ps0 = 0.f, pd0 = 0.f, ps1 = 0.f, pd1 = 0.f;
#pragma unroll
        for (int nt = 0; nt < 2; ++nt) {
            ps0 = fmaf(acc[nt][0], as[nt][0], fmaf(acc[nt][1], as[nt][1], ps0));
            pd0 = fmaf(acc[nt][0], ad[nt][0], fmaf(acc[nt][1], ad[nt][1], pd0));
            ps1 = fmaf(acc[nt][2], as[nt][0], fmaf(acc[nt][3], as[nt][1], ps1));
            pd1 = fmaf(acc[nt][2], ad[nt][0], fmaf(acc[nt][3], ad[nt][1], pd1));
        }
#pragma unroll
        for (int off = 1; off <= 2; off <<= 1) {
            ps0 += __shfl_xor_sync(0xFFFFFFFFu, ps0, off);
            pd0 += __shfl_xor_sync(0xFFFFFFFFu, pd0, off);
            ps1 += __shfl_xor_sync(0xFFFFFFFFu, ps1, off);
            pd1 += __shfl_xor_sync(0xFFFFFFFFu, pd1, off);
        }
        if (tg == 0) {
            sd_s[w * GBM + mt * 16 + g]     = ps0;
            sd_d[w * GBM + mt * 16 + g]     = pd0;
            sd_s[w * GBM + mt * 16 + g + 8] = ps1;
            sd_d[w * GBM + mt * 16 + g + 8] = pd1;
        }
    }
    __syncthreads();

    if (t < GBM) {
        float s = 0.f, d = 0.f;
#pragma unroll
        for (int i = 0; i < 8; ++i) {
            s += sd_s[i * GBM + t];
            d += sd_d[i * GBM + t];
        }
        g_s[rb + t] = s;
        g_d[rb + t] = d;
    }
}

// ---------------------------------------------------------------------------
// Kernel B: warp-per-node attention + aggregation.
// Phase 1: lane j scores edge j (edge 32 via broadcast); 1/denom folded into
// the weights, which go to warp-private smem as {w0,w0,w1,w1} + byte offsets.
// Phase 2: 33-edge gather, batched 4-wide for MLP; f32x2 FFMA2 accumulate.
// No block barriers (warp-private smem, __syncwarp only).
// ---------------------------------------------------------------------------
__global__ __launch_bounds__(256)
void gat_agg_kernel(const int* __restrict__ edges,
                    float* __restrict__ out) {
    __shared__ int    offs[8][EPN];
    __shared__ float4 wpr[8][EPN];

    const int t    = threadIdx.x;
    const int lane = t & 31;
    const int wi   = t >> 5;
    const int n    = blockIdx.x * 8 + wi;

    // --- Phase 1: scores ---
    const int2 e2  = __ldg(&((const int2*)edges)[n * EPN + lane]);
    const int dstv = e2.y;
    const float s0 = __ldg(&g_s[n]);
    const float s1 = __ldg(&g_s[NN + n]);

    float sc0 = s0 + __ldg(&g_d[dstv]);
    float sc1 = s1 + __ldg(&g_d[NN + dstv]);
    sc0 = (sc0 > 0.0f) ? sc0 : 0.2f * sc0;   // leaky_relu(0.2)
    sc1 = (sc1 > 0.0f) ? sc1 : 0.2f * sc1;
    const float w0v = expf(fminf(fmaxf(sc0, -2.0f), 2.0f));
    const float w1v = expf(fminf(fmaxf(sc1, -2.0f), 2.0f));

    // edge 32 (broadcast; computed redundantly by all lanes)
    const int d32 = __ldg(&edges[(n * EPN + 32) * 2 + 1]);
    float sx0 = s0 + __ldg(&g_d[d32]);
    float sx1 = s1 + __ldg(&g_d[NN + d32]);
    sx0 = (sx0 > 0.0f) ? sx0 : 0.2f * sx0;
    sx1 = (sx1 > 0.0f) ? sx1 : 0.2f * sx1;
    const float w032 = expf(fminf(fmaxf(sx0, -2.0f), 2.0f));
    const float w132 = expf(fminf(fmaxf(sx1, -2.0f), 2.0f));

    // denom over batch-0 scores (33 edges); fold 1/denom into weights
    float dn = w0v;
#pragma unroll
    for (int off = 16; off > 0; off >>= 1)
        dn += __shfl_xor_sync(0xFFFFFFFFu, dn, off);
    dn += w032;
    const float inv = 1.0f / dn;

    offs[wi][lane] = dstv * (int)sizeof(uint4) * 32;   // byte offset of h row
    {
        const float a = w0v * inv, b = w1v * inv;
        wpr[wi][lane] = make_float4(a, a, b, b);
    }
    if (lane == 0) {
        offs[wi][32] = d32 * (int)sizeof(uint4) * 32;
        const float a = w032 * inv, b = w132 * inv;
        wpr[wi][32] = make_float4(a, a, b, b);
    }
    __syncwarp();

    // --- Phase 2: gather, 4-edge batches ---
    const char* hbase = (const char*)g_hx + lane * 16;
    unsigned long long accA = 0ull, accB = 0ull;   // feats (0,1), (2,3)

#pragma unroll
    for (int eb = 0; eb < 32; eb += 4) {
        int    of[4];
        uint4  v[4];
        float4 wp[4];
#pragma unroll
        for (int k = 0; k < 4; ++k) of[k] = offs[wi][eb + k];
#pragma unroll
        for (int k = 0; k < 4; ++k) v[k] = *(const uint4*)(hbase + of[k]);
#pragma unroll
        for (int k = 0; k < 4; ++k) wp[k] = wpr[wi][eb + k];
#pragma unroll
        for (int k = 0; k < 4; ++k) {
            const unsigned long long c0p = packf2(wp[k].x, wp[k].y);
            const unsigned long long c1p = packf2(wp[k].z, wp[k].w);
            float2 f0a = __half22float2(*(__half2*)&v[k].x);
            float2 f0b = __half22float2(*(__half2*)&v[k].y);
            float2 f1a = __half22float2(*(__half2*)&v[k].z);
            float2 f1b = __half22float2(*(__half2*)&v[k].w);
            ffma2(accA, packf2(f0a.x, f0a.y), c0p);
            ffma2(accA, packf2(f1a.x, f1a.y), c1p);
            ffma2(accB, packf2(f0b.x, f0b.y), c0p);
            ffma2(accB, packf2(f1b.x, f1b.y), c1p);
        }
    }
    {   // edge 32
        const int of = offs[wi][32];
        const float4 wp = wpr[wi][32];
        const uint4 v = *(const uint4*)(hbase + of);
        const unsigned long long c0p = packf2(wp.x, wp.y);
        const unsigned long long c1p = packf2(wp.z, wp.w);
        float2 f0a = __half22float2(*(__half2*)&v.x);
        float2 f0b = __half22float2(*(__half2*)&v.y);
        float2 f1a = __half22float2(*(__half2*)&v.z);
        float2 f1b = __half22float2(*(__half2*)&v.w);
        ffma2(accA, packf2(f0a.x, f0a.y), c0p);
        ffma2(accA, packf2(f1a.x, f1a.y), c1p);
        ffma2(accB, packf2(f0b.x, f0b.y), c0p);
        ffma2(accB, packf2(f1b.x, f1b.y), c1p);
    }

    const float2 rA = unpackf2(accA);
    const float2 rB = unpackf2(accB);
    const float4 r = make_float4(rA.x, rA.y, rB.x, rB.y);
    ((float4*)(out + n * DD))[lane]           = r;   // batch 0
    ((float4*)(out + NN * DD + n * DD))[lane] = r;   // batch 1 (broadcast)
}

// ---------------------------------------------------------------------------
extern "C" void kernel_launch(void* const* d_in, const int* in_sizes, int n_in,
                              void* d_out, int out_size) {
    const float* inputs = (const float*)d_in[0];   // (2, 10000, 128)
    const float* W      = (const float*)d_in[1];   // (128, 128)
    const float* W_attn = (const float*)d_in[2];   // (256, 1)
    const int*   edges  = (const int*)d_in[3];     // (330000, 2)
    float*       out    = (float*)d_out;           // (2, 10000, 128)

    cudaFuncSetAttribute(gemm_sd_kernel,
                         cudaFuncAttributeMaxDynamicSharedMemorySize, GEMM_SMEM);

    gemm_sd_kernel<<<GNBLK, GTPB, GEMM_SMEM>>>(inputs, W, W_attn);
    gat_agg_kernel<<<NN / 8, 256>>>(edges, out);
}